// round 11
// baseline (speedup 1.0000x reference)
#include <cuda_runtime.h>
#include <cuda_bf16.h>
#include <mma.h>
#include <math.h>

using namespace nvcuda;

#define T_STEPS 128
#define BATCH   32
#define HIDDEN  1024
#define GATES   4096     // 4*HIDDEN
#define NCLS    32000
#define M_ALL   4096     // T_STEPS*BATCH
#define KSPLIT  8

// ---------------- scratch ----------------
__device__ float g_XG[(size_t)M_ALL * GATES];   // 64 MB
__device__ float g_HS[(size_t)M_ALL * HIDDEN];  // 16 MB
__device__ float g_part[KSPLIT * BATCH * GATES];// 4 MB partial gates
__device__ float g_c[BATCH * HIDDEN];
__device__ __align__(128) __nv_bfloat16 g_hh[BATCH * HIDDEN];
__device__ __align__(128) __nv_bfloat16 g_hl[BATCH * HIDDEN];
__device__ __align__(128) __nv_bfloat16 g_WhH[(size_t)HIDDEN * GATES];
__device__ __align__(128) __nv_bfloat16 g_WhL[(size_t)HIDDEN * GATES];

// ---------------- init ----------------
__global__ void init_state_kernel() {
    int i = blockIdx.x * blockDim.x + threadIdx.x;
    if (i < BATCH * HIDDEN) {
        g_c[i] = 0.0f;
        g_hh[i] = __float2bfloat16(0.0f);
        g_hl[i] = __float2bfloat16(0.0f);
    }
}

// ---------------- split Wh fp32 -> bf16 hi/lo ----------------
__global__ void split_wh_kernel(const float* __restrict__ Wh) {
    size_t o = ((size_t)blockIdx.x * 256 + threadIdx.x) * 4;
    float4 v = *(const float4*)(Wh + o);
    float vv[4] = {v.x, v.y, v.z, v.w};
#pragma unroll
    for (int j = 0; j < 4; j++) {
        __nv_bfloat16 h = __float2bfloat16(vv[j]);
        g_WhH[o + j] = h;
        g_WhL[o + j] = __float2bfloat16(vv[j] - __bfloat162float(h));
    }
}

// ==================== wmma GEMM constants =========================
#define PBK   32
#define ASTR  40      // A smem row stride (elements)
#define BSTR  136     // B smem row stride (elements)

// ---- embed: XG = emb[ids] @ Wx + b  (grid: bm fastest for Wx L2 reuse) ----
__global__ void __launch_bounds__(256, 1)
gemm_wmma_embed(const int* __restrict__ ids, const float* __restrict__ emb,
                const float* __restrict__ Wx, const float* __restrict__ bo) {
    __shared__ __align__(128) __nv_bfloat16 sAh[128 * ASTR];
    __shared__ __align__(128) __nv_bfloat16 sAl[128 * ASTR];
    __shared__ __align__(128) __nv_bfloat16 sBh[PBK * BSTR];
    __shared__ __align__(128) __nv_bfloat16 sBl[PBK * BSTR];
    __shared__ __align__(128) float sbias[16 * BSTR];
    __shared__ int ids_s[128];

    const int tid = threadIdx.x;
    const int wid = tid >> 5;
    const int bm = blockIdx.x * 128;   // fastest dim: A varies, B reused in L2
    const int bn = blockIdx.y * 128;
    const int wm = wid & 1;
    const int wn = wid >> 1;

    if (tid < 128) {
        ids_s[tid] = ids[bm + tid];
        float bv = bo[bn + tid];
#pragma unroll
        for (int r = 0; r < 16; r++) sbias[r * BSTR + tid] = bv;
    }
    __syncthreads();

    wmma::fragment<wmma::accumulator, 16, 16, 16, float> acc[4][2];
#pragma unroll
    for (int mi = 0; mi < 4; mi++)
#pragma unroll
        for (int ni = 0; ni < 2; ni++)
            wmma::load_matrix_sync(acc[mi][ni], sbias + wn * 32 + ni * 16, BSTR,
                                   wmma::mem_row_major);

    const int a_r = tid >> 3;
    const int a_c = (tid & 7) * 4;
    const int b_r = tid >> 5;
    const int b_c = (tid & 31) * 4;

    const float* arow_p[4];
#pragma unroll
    for (int s = 0; s < 4; s++)
        arow_p[s] = emb + (size_t)ids_s[s * 32 + a_r] * HIDDEN + a_c;

    float ra[4][4], rb[4][4];
#pragma unroll
    for (int s = 0; s < 4; s++) {
        *(float4*)ra[s] = *(const float4*)(arow_p[s]);
        *(float4*)rb[s] = *(const float4*)(Wx + (size_t)(s * 8 + b_r) * GATES + bn + b_c);
    }

    const int NCHUNK = HIDDEN / PBK;
#pragma unroll 1
    for (int i = 0; i < NCHUNK; i++) {
#pragma unroll
        for (int s = 0; s < 4; s++) {
            int arow = s * 32 + a_r;
#pragma unroll
            for (int j = 0; j < 4; j++) {
                float v = ra[s][j];
                __nv_bfloat16 h = __float2bfloat16(v);
                sAh[arow * ASTR + a_c + j] = h;
                sAl[arow * ASTR + a_c + j] = __float2bfloat16(v - __bfloat162float(h));
            }
            int brow = s * 8 + b_r;
#pragma unroll
            for (int j = 0; j < 4; j++) {
                float v = rb[s][j];
                __nv_bfloat16 h = __float2bfloat16(v);
                sBh[brow * BSTR + b_c + j] = h;
                sBl[brow * BSTR + b_c + j] = __float2bfloat16(v - __bfloat162float(h));
            }
        }
        __syncthreads();

        if (i + 1 < NCHUNK) {
            int k0 = (i + 1) * PBK;
#pragma unroll
            for (int s = 0; s < 4; s++) {
                *(float4*)ra[s] = *(const float4*)(arow_p[s] + k0);
                *(float4*)rb[s] = *(const float4*)(Wx + (size_t)(k0 + s * 8 + b_r) * GATES + bn + b_c);
            }
        }

#pragma unroll
        for (int kk = 0; kk < 2; kk++) {
            wmma::fragment<wmma::matrix_a, 16, 16, 16, __nv_bfloat16, wmma::row_major> afh[4], afl[4];
            wmma::fragment<wmma::matrix_b, 16, 16, 16, __nv_bfloat16, wmma::row_major> bfh[2], bfl[2];
#pragma unroll
            for (int mi = 0; mi < 4; mi++) {
                const int ao = (wm * 64 + mi * 16) * ASTR + kk * 16;
                wmma::load_matrix_sync(afh[mi], sAh + ao, ASTR);
                wmma::load_matrix_sync(afl[mi], sAl + ao, ASTR);
            }
#pragma unroll
            for (int ni = 0; ni < 2; ni++) {
                const int bo2 = (kk * 16) * BSTR + wn * 32 + ni * 16;
                wmma::load_matrix_sync(bfh[ni], sBh + bo2, BSTR);
                wmma::load_matrix_sync(bfl[ni], sBl + bo2, BSTR);
            }
#pragma unroll
            for (int mi = 0; mi < 4; mi++)
#pragma unroll
                for (int ni = 0; ni < 2; ni++) {
                    wmma::mma_sync(acc[mi][ni], afh[mi], bfh[ni], acc[mi][ni]);
                    wmma::mma_sync(acc[mi][ni], afh[mi], bfl[ni], acc[mi][ni]);
                    wmma::mma_sync(acc[mi][ni], afl[mi], bfh[ni], acc[mi][ni]);
                }
        }
        __syncthreads();
    }

#pragma unroll
    for (int mi = 0; mi < 4; mi++)
#pragma unroll
        for (int ni = 0; ni < 2; ni++) {
            float* op = g_XG + (size_t)(bm + wm * 64 + mi * 16) * GATES + bn + wn * 32 + ni * 16;
            wmma::store_matrix_sync(op, acc[mi][ni], GATES, wmma::mem_row_major);
        }
}

// ---- LSTM step gemm: K-split x8, register-prefetch pipelined --------------
__global__ void __launch_bounds__(256, 1)
lstm_wmma_ks_kernel() {
    __shared__ __align__(128) __nv_bfloat16 sAh[32 * ASTR];
    __shared__ __align__(128) __nv_bfloat16 sAl[32 * ASTR];
    __shared__ __align__(128) __nv_bfloat16 sBh[PBK * BSTR];
    __shared__ __align__(128) __nv_bfloat16 sBl[PBK * BSTR];

    const int tid = threadIdx.x;
    const int wid = tid >> 5;
    const int bn = blockIdx.x * 128;
    const int ks = blockIdx.y;
    const int kbase = ks * (HIDDEN / KSPLIT);   // 128 per split
    const int wm = wid & 1;
    const int wn = wid >> 1;

    wmma::fragment<wmma::accumulator, 16, 16, 16, float> acc[2];
#pragma unroll
    for (int ni = 0; ni < 2; ni++) wmma::fill_fragment(acc[ni], 0.0f);

    const int a_t = tid & 127;
    const int a_r = a_t >> 2;
    const int a_c8 = (a_t & 3) * 8;
    const __nv_bfloat16* __restrict__ aptr =
        (tid < 128 ? g_hh : g_hl) + a_r * HIDDEN + a_c8;
    __nv_bfloat16* const a_s = (tid < 128 ? sAh : sAl) + a_r * ASTR + a_c8;

    int b_r[2], b_c8[2];
#pragma unroll
    for (int it = 0; it < 2; it++) {
        int idx = tid + it * 256;
        b_r[it] = idx >> 4;
        b_c8[it] = (idx & 15) * 8;
    }

    uint4 rA, rBh[2], rBl[2];
    rA = *(const uint4*)(aptr + kbase);
#pragma unroll
    for (int it = 0; it < 2; it++) {
        size_t go = (size_t)(kbase + b_r[it]) * GATES + bn + b_c8[it];
        rBh[it] = *(const uint4*)(g_WhH + go);
        rBl[it] = *(const uint4*)(g_WhL + go);
    }

    const int NCHUNK = (HIDDEN / KSPLIT) / PBK;   // 4
#pragma unroll 1
    for (int i = 0; i < NCHUNK; i++) {
        *(uint4*)a_s = rA;
#pragma unroll
        for (int it = 0; it < 2; it++) {
            *(uint4*)(sBh + b_r[it] * BSTR + b_c8[it]) = rBh[it];
            *(uint4*)(sBl + b_r[it] * BSTR + b_c8[it]) = rBl[it];
        }
        __syncthreads();

        if (i + 1 < NCHUNK) {
            const int k0 = kbase + (i + 1) * PBK;
            rA = *(const uint4*)(aptr + k0);
#pragma unroll
            for (int it = 0; it < 2; it++) {
                size_t go = (size_t)(k0 + b_r[it]) * GATES + bn + b_c8[it];
                rBh[it] = *(const uint4*)(g_WhH + go);
                rBl[it] = *(const uint4*)(g_WhL + go);
            }
        }

#pragma unroll
        for (int kk = 0; kk < 2; kk++) {
            wmma::fragment<wmma::matrix_a, 16, 16, 16, __nv_bfloat16, wmma::row_major> afh, afl;
            wmma::fragment<wmma::matrix_b, 16, 16, 16, __nv_bfloat16, wmma::row_major> bfh[2], bfl[2];
            const int ao = (wm * 16) * ASTR + kk * 16;
            wmma::load_matrix_sync(afh, sAh + ao, ASTR);
            wmma::load_matrix_sync(afl, sAl + ao, ASTR);
#pragma unroll
            for (int ni = 0; ni < 2; ni++) {
                const int bo2 = (kk * 16) * BSTR + wn * 32 + ni * 16;
                wmma::load_matrix_sync(bfh[ni], sBh + bo2, BSTR);
                wmma::load_matrix_sync(bfl[ni], sBl + bo2, BSTR);
            }
#pragma unroll
            for (int ni = 0; ni < 2; ni++) {
                wmma::mma_sync(acc[ni], afh, bfh[ni], acc[ni]);
                wmma::mma_sync(acc[ni], afh, bfl[ni], acc[ni]);
                wmma::mma_sync(acc[ni], afl, bfh[ni], acc[ni]);
            }
        }
        __syncthreads();
    }

    float* pp = g_part + (size_t)ks * BATCH * GATES;
#pragma unroll
    for (int ni = 0; ni < 2; ni++)
        wmma::store_matrix_sync(pp + (size_t)(wm * 16) * GATES + bn + wn * 32 + ni * 16,
                                acc[ni], GATES, wmma::mem_row_major);
}

// ---- fused reduce + pointwise ----------------------------------------------
__global__ void lstm_reduce_point_kernel(int t) {
    const int idx = blockIdx.x * 256 + threadIdx.x;   // 0..32767
    const int unit = idx & (HIDDEN - 1);
    const int r = idx >> 10;

    const float* __restrict__ XGt = g_XG + (size_t)t * BATCH * GATES + (size_t)r * GATES;
    float gate[4];
#pragma unroll
    for (int g = 0; g < 4; g++) {
        const int col = unit + (g << 10);
        float s = XGt[col];
#pragma unroll
        for (int k = 0; k < KSPLIT; k++)
            s += g_part[(size_t)k * BATCH * GATES + (size_t)r * GATES + col];
        gate[g] = s;
    }

    float cold = g_c[idx];
    float si = 1.0f / (1.0f + expf(-gate[0]));
    float sf = 1.0f / (1.0f + expf(-gate[1]));
    float tg = tanhf(gate[2]);
    float so = 1.0f / (1.0f + expf(-gate[3]));
    float cn = sf * cold + si * tg;
    float hn = so * tanhf(cn);

    g_c[idx] = cn;
    g_HS[((size_t)t * BATCH + r) * HIDDEN + unit] = hn;
    __nv_bfloat16 hh = __float2bfloat16(hn);
    g_hh[idx] = hh;
    g_hl[idx] = __float2bfloat16(hn - __bfloat162float(hh));
}

// ---- projection: out = HS @ Wo + bo  (grid: bm fastest for Wo L2 reuse) ----
__global__ void __launch_bounds__(256, 1)
gemm_wmma_proj(const float* __restrict__ Wo, const float* __restrict__ bo,
               float* __restrict__ out) {
    __shared__ __align__(128) __nv_bfloat16 sAh[128 * ASTR];
    __shared__ __align__(128) __nv_bfloat16 sAl[128 * ASTR];
    __shared__ __align__(128) __nv_bfloat16 sBh[PBK * BSTR];
    __shared__ __align__(128) __nv_bfloat16 sBl[PBK * BSTR];
    __shared__ __align__(128) float sbias[16 * BSTR];

    const int tid = threadIdx.x;
    const int wid = tid >> 5;
    const int bm = blockIdx.x * 128;   // fastest dim: A varies, B reused in L2
    const int bn = blockIdx.y * 128;
    const int wm = wid & 1;
    const int wn = wid >> 1;

    if (tid < 128) {
        float bv = bo[bn + tid];
#pragma unroll
        for (int r = 0; r < 16; r++) sbias[r * BSTR + tid] = bv;
    }
    __syncthreads();

    wmma::fragment<wmma::accumulator, 16, 16, 16, float> acc[4][2];
#pragma unroll
    for (int mi = 0; mi < 4; mi++)
#pragma unroll
        for (int ni = 0; ni < 2; ni++)
            wmma::load_matrix_sync(acc[mi][ni], sbias + wn * 32 + ni * 16, BSTR,
                                   wmma::mem_row_major);

    const int a_r = tid >> 3;
    const int a_c = (tid & 7) * 4;
    const int b_r = tid >> 5;
    const int b_c = (tid & 31) * 4;

    float ra[4][4], rb[4][4];
#pragma unroll
    for (int s = 0; s < 4; s++) {
        *(float4*)ra[s] = *(const float4*)(g_HS + (size_t)(bm + s * 32 + a_r) * HIDDEN + a_c);
        *(float4*)rb[s] = *(const float4*)(Wo + (size_t)(s * 8 + b_r) * NCLS + bn + b_c);
    }

    const int NCHUNK = HIDDEN / PBK;
#pragma unroll 1
    for (int i = 0; i < NCHUNK; i++) {
#pragma unroll
        for (int s = 0; s < 4; s++) {
            int arow = s * 32 + a_r;
#pragma unroll
            for (int j = 0; j < 4; j++) {
                float v = ra[s][j];
                __nv_bfloat16 h = __float2bfloat16(v);
                sAh[arow * ASTR + a_c + j] = h;
                sAl[arow * ASTR + a_c + j] = __float2bfloat16(v - __bfloat162float(h));
            }
            int brow = s * 8 + b_r;
#pragma unroll
            for (int j = 0; j < 4; j++) {
                float v = rb[s][j];
                __nv_bfloat16 h = __float2bfloat16(v);
                sBh[brow * BSTR + b_c + j] = h;
                sBl[brow * BSTR + b_c + j] = __float2bfloat16(v - __bfloat162float(h));
            }
        }
        __syncthreads();

        if (i + 1 < NCHUNK) {
            int k0 = (i + 1) * PBK;
#pragma unroll
            for (int s = 0; s < 4; s++) {
                *(float4*)ra[s] = *(const float4*)(g_HS + (size_t)(bm + s * 32 + a_r) * HIDDEN + k0 + a_c);
                *(float4*)rb[s] = *(const float4*)(Wo + (size_t)(k0 + s * 8 + b_r) * NCLS + bn + b_c);
            }
        }

#pragma unroll
        for (int kk = 0; kk < 2; kk++) {
            wmma::fragment<wmma::matrix_a, 16, 16, 16, __nv_bfloat16, wmma::row_major> afh[4], afl[4];
            wmma::fragment<wmma::matrix_b, 16, 16, 16, __nv_bfloat16, wmma::row_major> bfh[2], bfl[2];
#pragma unroll
            for (int mi = 0; mi < 4; mi++) {
                const int ao = (wm * 64 + mi * 16) * ASTR + kk * 16;
                wmma::load_matrix_sync(afh[mi], sAh + ao, ASTR);
                wmma::load_matrix_sync(afl[mi], sAl + ao, ASTR);
            }
#pragma unroll
            for (int ni = 0; ni < 2; ni++) {
                const int bo2 = (kk * 16) * BSTR + wn * 32 + ni * 16;
                wmma::load_matrix_sync(bfh[ni], sBh + bo2, BSTR);
                wmma::load_matrix_sync(bfl[ni], sBl + bo2, BSTR);
            }
#pragma unroll
            for (int mi = 0; mi < 4; mi++)
#pragma unroll
                for (int ni = 0; ni < 2; ni++) {
                    wmma::mma_sync(acc[mi][ni], afh[mi], bfh[ni], acc[mi][ni]);
                    wmma::mma_sync(acc[mi][ni], afh[mi], bfl[ni], acc[mi][ni]);
                    wmma::mma_sync(acc[mi][ni], afl[mi], bfh[ni], acc[mi][ni]);
                }
        }
        __syncthreads();
    }

#pragma unroll
    for (int mi = 0; mi < 4; mi++)
#pragma unroll
        for (int ni = 0; ni < 2; ni++) {
            float* op = out + (size_t)(bm + wm * 64 + mi * 16) * NCLS + bn + wn * 32 + ni * 16;
            wmma::store_matrix_sync(op, acc[mi][ni], NCLS, wmma::mem_row_major);
        }
}

// --------------------------------------------------------------------------
extern "C" void kernel_launch(void* const* d_in, const int* in_sizes, int n_in,
                              void* d_out, int out_size) {
    const int*   input = (const int*)d_in[0];
    const float* emb   = (const float*)d_in[1];
    const float* W_x   = (const float*)d_in[2];
    const float* W_h   = (const float*)d_in[3];
    const float* b     = (const float*)d_in[4];
    const float* W_h2o = (const float*)d_in[5];
    const float* b_o   = (const float*)d_in[6];
    float* out = (float*)d_out;

    (void)in_sizes; (void)n_in; (void)out_size;

    init_state_kernel<<<(BATCH * HIDDEN + 255) / 256, 256>>>();
    split_wh_kernel<<<(HIDDEN * GATES / 4 + 255) / 256, 256>>>(W_h);

    {
        dim3 grid(M_ALL / 128, GATES / 128);  // (32, 32) — bm fastest
        gemm_wmma_embed<<<grid, 256>>>(input, emb, W_x, b);
    }

    for (int t = 0; t < T_STEPS; t++) {
        dim3 gg(GATES / 128, KSPLIT);         // (32, 8) = 256 CTAs
        lstm_wmma_ks_kernel<<<gg, 256>>>();
        lstm_reduce_point_kernel<<<BATCH * HIDDEN / 256, 256>>>(t);
    }

    {
        dim3 grid(M_ALL / 128, NCLS / 128);   // (32, 250) — bm fastest
        gemm_wmma_proj<<<grid, 256>>>(W_h2o, b_o, out);
    }
}

// round 14
// speedup vs baseline: 1.0345x; 1.0345x over previous
#include <cuda_runtime.h>
#include <cuda_bf16.h>
#include <mma.h>
#include <math.h>
#include <cstdint>

using namespace nvcuda;

#define T_STEPS 128
#define BATCH   32
#define HIDDEN  1024
#define GATES   4096     // 4*HIDDEN
#define NCLS    32000
#define M_ALL   4096     // T_STEPS*BATCH
#define KSPLIT  4

// ---------------- scratch (total ~98 MiB — stay under the ~100MiB-passing regime) ----
__device__ float g_XG[(size_t)M_ALL * GATES];   // 64 MB
__device__ float g_part[KSPLIT * BATCH * GATES];// 2 MB
__device__ float g_c[BATCH * HIDDEN];
__device__ __align__(128) __nv_bfloat16 g_hh[BATCH * HIDDEN];
__device__ __align__(128) __nv_bfloat16 g_hl[BATCH * HIDDEN];
__device__ __align__(128) __nv_bfloat16 g_HSh[(size_t)M_ALL * HIDDEN];  // 8 MB
__device__ __align__(128) __nv_bfloat16 g_HSl[(size_t)M_ALL * HIDDEN];  // 8 MB
__device__ __align__(128) __nv_bfloat16 g_WhH[(size_t)HIDDEN * GATES];  // 8 MB
__device__ __align__(128) __nv_bfloat16 g_WhL[(size_t)HIDDEN * GATES];  // 8 MB

// ---------------- helpers: packed fp32x4 -> bf16x2 hi/lo ----------------
__device__ __forceinline__ void split4(const float4 v, uint2& hi, uint2& lo) {
    __nv_bfloat162 h01 = __floats2bfloat162_rn(v.x, v.y);
    __nv_bfloat162 h23 = __floats2bfloat162_rn(v.z, v.w);
    float2 f01 = __bfloat1622float2(h01);
    float2 f23 = __bfloat1622float2(h23);
    __nv_bfloat162 l01 = __floats2bfloat162_rn(v.x - f01.x, v.y - f01.y);
    __nv_bfloat162 l23 = __floats2bfloat162_rn(v.z - f23.x, v.w - f23.y);
    hi.x = *(uint32_t*)&h01; hi.y = *(uint32_t*)&h23;
    lo.x = *(uint32_t*)&l01; lo.y = *(uint32_t*)&l23;
}

// ---------------- init ----------------
__global__ void init_state_kernel() {
    int i = blockIdx.x * blockDim.x + threadIdx.x;
    if (i < BATCH * HIDDEN) {
        g_c[i] = 0.0f;
        g_hh[i] = __float2bfloat16(0.0f);
        g_hl[i] = __float2bfloat16(0.0f);
    }
}

// ---------------- split Wh fp32 -> bf16 hi/lo ----------------
__global__ void split_wh_kernel(const float* __restrict__ Wh) {
    size_t o = ((size_t)blockIdx.x * 256 + threadIdx.x) * 4;
    float4 v = *(const float4*)(Wh + o);
    uint2 hi, lo;
    split4(v, hi, lo);
    *(uint2*)(g_WhH + o) = hi;
    *(uint2*)(g_WhL + o) = lo;
}

// ==================== wmma GEMM constants =========================
#define PBK   32
#define ASTR  40      // A smem row stride (elements)
#define BSTR  136     // B smem row stride (elements)

// ---- embed: XG = emb[ids] @ Wx + b (packed conversions) -------------------
__global__ void __launch_bounds__(256, 1)
gemm_wmma_embed(const int* __restrict__ ids, const float* __restrict__ emb,
                const float* __restrict__ Wx, const float* __restrict__ bo) {
    __shared__ __align__(128) __nv_bfloat16 sAh[128 * ASTR];
    __shared__ __align__(128) __nv_bfloat16 sAl[128 * ASTR];
    __shared__ __align__(128) __nv_bfloat16 sBh[PBK * BSTR];
    __shared__ __align__(128) __nv_bfloat16 sBl[PBK * BSTR];
    __shared__ __align__(128) float sbias[16 * BSTR];
    __shared__ int ids_s[128];

    const int tid = threadIdx.x;
    const int wid = tid >> 5;
    const int bm = blockIdx.x * 128;
    const int bn = blockIdx.y * 128;
    const int wm = wid & 1;
    const int wn = wid >> 1;

    if (tid < 128) {
        ids_s[tid] = ids[bm + tid];
        float bv = bo[bn + tid];
#pragma unroll
        for (int r = 0; r < 16; r++) sbias[r * BSTR + tid] = bv;
    }
    __syncthreads();

    wmma::fragment<wmma::accumulator, 16, 16, 16, float> acc[4][2];
#pragma unroll
    for (int mi = 0; mi < 4; mi++)
#pragma unroll
        for (int ni = 0; ni < 2; ni++)
            wmma::load_matrix_sync(acc[mi][ni], sbias + wn * 32 + ni * 16, BSTR,
                                   wmma::mem_row_major);

    const int a_r = tid >> 3;
    const int a_c = (tid & 7) * 4;
    const int b_r = tid >> 5;
    const int b_c = (tid & 31) * 4;

    const float* arow_p[4];
#pragma unroll
    for (int s = 0; s < 4; s++)
        arow_p[s] = emb + (size_t)ids_s[s * 32 + a_r] * HIDDEN + a_c;

    float4 ra[4], rb[4];
#pragma unroll
    for (int s = 0; s < 4; s++) {
        ra[s] = *(const float4*)(arow_p[s]);
        rb[s] = *(const float4*)(Wx + (size_t)(s * 8 + b_r) * GATES + bn + b_c);
    }

    const int NCHUNK = HIDDEN / PBK;
#pragma unroll 1
    for (int i = 0; i < NCHUNK; i++) {
#pragma unroll
        for (int s = 0; s < 4; s++) {
            uint2 hi, lo;
            split4(ra[s], hi, lo);
            const int arow = s * 32 + a_r;
            *(uint2*)(sAh + arow * ASTR + a_c) = hi;
            *(uint2*)(sAl + arow * ASTR + a_c) = lo;
            split4(rb[s], hi, lo);
            const int brow = s * 8 + b_r;
            *(uint2*)(sBh + brow * BSTR + b_c) = hi;
            *(uint2*)(sBl + brow * BSTR + b_c) = lo;
        }
        __syncthreads();

        if (i + 1 < NCHUNK) {
            int k0 = (i + 1) * PBK;
#pragma unroll
            for (int s = 0; s < 4; s++) {
                ra[s] = *(const float4*)(arow_p[s] + k0);
                rb[s] = *(const float4*)(Wx + (size_t)(k0 + s * 8 + b_r) * GATES + bn + b_c);
            }
        }

#pragma unroll
        for (int kk = 0; kk < 2; kk++) {
            wmma::fragment<wmma::matrix_a, 16, 16, 16, __nv_bfloat16, wmma::row_major> afh[4], afl[4];
            wmma::fragment<wmma::matrix_b, 16, 16, 16, __nv_bfloat16, wmma::row_major> bfh[2], bfl[2];
#pragma unroll
            for (int mi = 0; mi < 4; mi++) {
                const int ao = (wm * 64 + mi * 16) * ASTR + kk * 16;
                wmma::load_matrix_sync(afh[mi], sAh + ao, ASTR);
                wmma::load_matrix_sync(afl[mi], sAl + ao, ASTR);
            }
#pragma unroll
            for (int ni = 0; ni < 2; ni++) {
                const int bo2 = (kk * 16) * BSTR + wn * 32 + ni * 16;
                wmma::load_matrix_sync(bfh[ni], sBh + bo2, BSTR);
                wmma::load_matrix_sync(bfl[ni], sBl + bo2, BSTR);
            }
#pragma unroll
            for (int mi = 0; mi < 4; mi++)
#pragma unroll
                for (int ni = 0; ni < 2; ni++) {
                    wmma::mma_sync(acc[mi][ni], afh[mi], bfh[ni], acc[mi][ni]);
                    wmma::mma_sync(acc[mi][ni], afh[mi], bfl[ni], acc[mi][ni]);
                    wmma::mma_sync(acc[mi][ni], afl[mi], bfh[ni], acc[mi][ni]);
                }
        }
        __syncthreads();
    }

#pragma unroll
    for (int mi = 0; mi < 4; mi++)
#pragma unroll
        for (int ni = 0; ni < 2; ni++) {
            float* op = g_XG + (size_t)(bm + wm * 64 + mi * 16) * GATES + bn + wn * 32 + ni * 16;
            wmma::store_matrix_sync(op, acc[mi][ni], GATES, wmma::mem_row_major);
        }
}

// ---- LSTM step gemm (R10-proven): K-split x4, register-prefetch ----------
__global__ void __launch_bounds__(256, 1)
lstm_wmma_ks_kernel() {
    __shared__ __align__(128) __nv_bfloat16 sAh[32 * ASTR];
    __shared__ __align__(128) __nv_bfloat16 sAl[32 * ASTR];
    __shared__ __align__(128) __nv_bfloat16 sBh[PBK * BSTR];
    __shared__ __align__(128) __nv_bfloat16 sBl[PBK * BSTR];

    const int tid = threadIdx.x;
    const int wid = tid >> 5;
    const int bn = blockIdx.x * 128;
    const int ks = blockIdx.y;
    const int kbase = ks * (HIDDEN / KSPLIT);   // 256 per split
    const int wm = wid & 1;
    const int wn = wid >> 1;

    wmma::fragment<wmma::accumulator, 16, 16, 16, float> acc[2];
#pragma unroll
    for (int ni = 0; ni < 2; ni++) wmma::fill_fragment(acc[ni], 0.0f);

    const int a_t = tid & 127;
    const int a_r = a_t >> 2;
    const int a_c8 = (a_t & 3) * 8;
    const __nv_bfloat16* __restrict__ aptr =
        (tid < 128 ? g_hh : g_hl) + a_r * HIDDEN + a_c8;
    __nv_bfloat16* const a_s = (tid < 128 ? sAh : sAl) + a_r * ASTR + a_c8;

    int b_r[2], b_c8[2];
#pragma unroll
    for (int it = 0; it < 2; it++) {
        int idx = tid + it * 256;
        b_r[it] = idx >> 4;
        b_c8[it] = (idx & 15) * 8;
    }

    uint4 rA, rBh[2], rBl[2];
    rA = *(const uint4*)(aptr + kbase);
#pragma unroll
    for (int it = 0; it < 2; it++) {
        size_t go = (size_t)(kbase + b_r[it]) * GATES + bn + b_c8[it];
        rBh[it] = *(const uint4*)(g_WhH + go);
        rBl[it] = *(const uint4*)(g_WhL + go);
    }

    const int NCHUNK = (HIDDEN / KSPLIT) / PBK;   // 8
#pragma unroll 1
    for (int i = 0; i < NCHUNK; i++) {
        *(uint4*)a_s = rA;
#pragma unroll
        for (int it = 0; it < 2; it++) {
            *(uint4*)(sBh + b_r[it] * BSTR + b_c8[it]) = rBh[it];
            *(uint4*)(sBl + b_r[it] * BSTR + b_c8[it]) = rBl[it];
        }
        __syncthreads();

        if (i + 1 < NCHUNK) {
            const int k0 = kbase + (i + 1) * PBK;
            rA = *(const uint4*)(aptr + k0);
#pragma unroll
            for (int it = 0; it < 2; it++) {
                size_t go = (size_t)(k0 + b_r[it]) * GATES + bn + b_c8[it];
                rBh[it] = *(const uint4*)(g_WhH + go);
                rBl[it] = *(const uint4*)(g_WhL + go);
            }
        }

#pragma unroll
        for (int kk = 0; kk < 2; kk++) {
            wmma::fragment<wmma::matrix_a, 16, 16, 16, __nv_bfloat16, wmma::row_major> afh, afl;
            wmma::fragment<wmma::matrix_b, 16, 16, 16, __nv_bfloat16, wmma::row_major> bfh[2], bfl[2];
            const int ao = (wm * 16) * ASTR + kk * 16;
            wmma::load_matrix_sync(afh, sAh + ao, ASTR);
            wmma::load_matrix_sync(afl, sAl + ao, ASTR);
#pragma unroll
            for (int ni = 0; ni < 2; ni++) {
                const int bo2 = (kk * 16) * BSTR + wn * 32 + ni * 16;
                wmma::load_matrix_sync(bfh[ni], sBh + bo2, BSTR);
                wmma::load_matrix_sync(bfl[ni], sBl + bo2, BSTR);
            }
#pragma unroll
            for (int ni = 0; ni < 2; ni++) {
                wmma::mma_sync(acc[ni], afh, bfh[ni], acc[ni]);
                wmma::mma_sync(acc[ni], afh, bfl[ni], acc[ni]);
                wmma::mma_sync(acc[ni], afl, bfh[ni], acc[ni]);
            }
        }
        __syncthreads();
    }

    float* pp = g_part + (size_t)ks * BATCH * GATES;
#pragma unroll
    for (int ni = 0; ni < 2; ni++)
        wmma::store_matrix_sync(pp + (size_t)(wm * 16) * GATES + bn + wn * 32 + ni * 16,
                                acc[ni], GATES, wmma::mem_row_major);
}

// ---- fused reduce + pointwise; h history stored directly as bf16 hi/lo ----
__global__ void lstm_reduce_point_kernel(int t) {
    const int idx = blockIdx.x * 256 + threadIdx.x;   // 0..32767
    const int unit = idx & (HIDDEN - 1);
    const int r = idx >> 10;

    const float* __restrict__ XGt = g_XG + (size_t)t * BATCH * GATES + (size_t)r * GATES;
    float gate[4];
#pragma unroll
    for (int g = 0; g < 4; g++) {
        const int col = unit + (g << 10);
        float s = XGt[col];
#pragma unroll
        for (int k = 0; k < KSPLIT; k++)
            s += g_part[(size_t)k * BATCH * GATES + (size_t)r * GATES + col];
        gate[g] = s;
    }

    float cold = g_c[idx];
    float si = 1.0f / (1.0f + expf(-gate[0]));
    float sf = 1.0f / (1.0f + expf(-gate[1]));
    float tg = tanhf(gate[2]);
    float so = 1.0f / (1.0f + expf(-gate[3]));
    float cn = sf * cold + si * tg;
    float hn = so * tanhf(cn);

    g_c[idx] = cn;
    __nv_bfloat16 hh = __float2bfloat16(hn);
    __nv_bfloat16 hl = __float2bfloat16(hn - __bfloat162float(hh));
    g_hh[idx] = hh;
    g_hl[idx] = hl;
    const size_t ho = ((size_t)t * BATCH + r) * HIDDEN + unit;
    g_HSh[ho] = hh;
    g_HSl[ho] = hl;
}

// ---- projection: out = HSbf16 @ Wo + bo (A pure bf16; B packed-convert) ----
__global__ void __launch_bounds__(256, 1)
gemm_wmma_proj(const float* __restrict__ Wo, const float* __restrict__ bo,
               float* __restrict__ out) {
    __shared__ __align__(128) __nv_bfloat16 sAh[128 * ASTR];
    __shared__ __align__(128) __nv_bfloat16 sAl[128 * ASTR];
    __shared__ __align__(128) __nv_bfloat16 sBh[PBK * BSTR];
    __shared__ __align__(128) __nv_bfloat16 sBl[PBK * BSTR];
    __shared__ __align__(128) float sbias[16 * BSTR];

    const int tid = threadIdx.x;
    const int wid = tid >> 5;
    const int bm = blockIdx.x * 128;   // bm fastest: HS bf16 (16MB) L2-resident
    const int bn = blockIdx.y * 128;
    const int wm = wid & 1;
    const int wn = wid >> 1;

    if (tid < 128) {
        float bv = bo[bn + tid];
#pragma unroll
        for (int r = 0; r < 16; r++) sbias[r * BSTR + tid] = bv;
    }
    __syncthreads();

    wmma::fragment<wmma::accumulator, 16, 16, 16, float> acc[4][2];
#pragma unroll
    for (int mi = 0; mi < 4; mi++)
#pragma unroll
        for (int ni = 0; ni < 2; ni++)
            wmma::load_matrix_sync(acc[mi][ni], sbias + wn * 32 + ni * 16, BSTR,
                                   wmma::mem_row_major);

    // A coords: 512 uint4 (128 rows x 4 col-groups), 2 per thread, hi+lo each
    int a_r[2], a_c8[2];
#pragma unroll
    for (int it = 0; it < 2; it++) {
        int idx = tid + it * 256;
        a_r[it] = idx >> 2;
        a_c8[it] = (idx & 3) * 8;
    }
    // B coords: fp32 rows, 4 float4 per thread (32 rows x 32 float4-groups)
    const int b_r = tid >> 5;
    const int b_c = (tid & 31) * 4;

    uint4 rAh[2], rAl[2];
    float4 rb[4];
#pragma unroll
    for (int it = 0; it < 2; it++) {
        size_t ao = (size_t)(bm + a_r[it]) * HIDDEN + a_c8[it];
        rAh[it] = *(const uint4*)(g_HSh + ao);
        rAl[it] = *(const uint4*)(g_HSl + ao);
    }
#pragma unroll
    for (int s = 0; s < 4; s++)
        rb[s] = *(const float4*)(Wo + (size_t)(s * 8 + b_r) * NCLS + bn + b_c);

    const int NCHUNK = HIDDEN / PBK;   // 32
#pragma unroll 1
    for (int i = 0; i < NCHUNK; i++) {
#pragma unroll
        for (int it = 0; it < 2; it++) {
            *(uint4*)(sAh + a_r[it] * ASTR + a_c8[it]) = rAh[it];
            *(uint4*)(sAl + a_r[it] * ASTR + a_c8[it]) = rAl[it];
        }
#pragma unroll
        for (int s = 0; s < 4; s++) {
            uint2 hi, lo;
            split4(rb[s], hi, lo);
            const int brow = s * 8 + b_r;
            *(uint2*)(sBh + brow * BSTR + b_c) = hi;
            *(uint2*)(sBl + brow * BSTR + b_c) = lo;
        }
        __syncthreads();

        if (i + 1 < NCHUNK) {
            const int k0 = (i + 1) * PBK;
#pragma unroll
            for (int it = 0; it < 2; it++) {
                size_t ao = (size_t)(bm + a_r[it]) * HIDDEN + k0 + a_c8[it];
                rAh[it] = *(const uint4*)(g_HSh + ao);
                rAl[it] = *(const uint4*)(g_HSl + ao);
            }
#pragma unroll
            for (int s = 0; s < 4; s++)
                rb[s] = *(const float4*)(Wo + (size_t)(k0 + s * 8 + b_r) * NCLS + bn + b_c);
        }

#pragma unroll
        for (int kk = 0; kk < 2; kk++) {
            wmma::fragment<wmma::matrix_a, 16, 16, 16, __nv_bfloat16, wmma::row_major> afh[4], afl[4];
            wmma::fragment<wmma::matrix_b, 16, 16, 16, __nv_bfloat16, wmma::row_major> bfh[2], bfl[2];
#pragma unroll
            for (int mi = 0; mi < 4; mi++) {
                const int ao = (wm * 64 + mi * 16) * ASTR + kk * 16;
                wmma::load_matrix_sync(afh[mi], sAh + ao, ASTR);
                wmma::load_matrix_sync(afl[mi], sAl + ao, ASTR);
            }
#pragma unroll
            for (int ni = 0; ni < 2; ni++) {
                const int bo2 = (kk * 16) * BSTR + wn * 32 + ni * 16;
                wmma::load_matrix_sync(bfh[ni], sBh + bo2, BSTR);
                wmma::load_matrix_sync(bfl[ni], sBl + bo2, BSTR);
            }
#pragma unroll
            for (int mi = 0; mi < 4; mi++)
#pragma unroll
                for (int ni = 0; ni < 2; ni++) {
                    wmma::mma_sync(acc[mi][ni], afh[mi], bfh[ni], acc[mi][ni]);
                    wmma::mma_sync(acc[mi][ni], afh[mi], bfl[ni], acc[mi][ni]);
                    wmma::mma_sync(acc[mi][ni], afl[mi], bfh[ni], acc[mi][ni]);
                }
        }
        __syncthreads();
    }

#pragma unroll
    for (int mi = 0; mi < 4; mi++)
#pragma unroll
        for (int ni = 0; ni < 2; ni++) {
            float* op = out + (size_t)(bm + wm * 64 + mi * 16) * NCLS + bn + wn * 32 + ni * 16;
            wmma::store_matrix_sync(op, acc[mi][ni], NCLS, wmma::mem_row_major);
        }
}

// --------------------------------------------------------------------------
extern "C" void kernel_launch(void* const* d_in, const int* in_sizes, int n_in,
                              void* d_out, int out_size) {
    const int*   input = (const int*)d_in[0];
    const float* emb   = (const float*)d_in[1];
    const float* W_x   = (const float*)d_in[2];
    const float* W_h   = (const float*)d_in[3];
    const float* b     = (const float*)d_in[4];
    const float* W_h2o = (const float*)d_in[5];
    const float* b_o   = (const float*)d_in[6];
    float* out = (float*)d_out;

    (void)in_sizes; (void)n_in; (void)out_size;

    init_state_kernel<<<(BATCH * HIDDEN + 255) / 256, 256>>>();
    split_wh_kernel<<<HIDDEN * GATES / 1024, 256>>>(W_h);

    {
        dim3 grid(M_ALL / 128, GATES / 128);  // (32, 32)
        gemm_wmma_embed<<<grid, 256>>>(input, emb, W_x, b);
    }

    for (int t = 0; t < T_STEPS; t++) {
        dim3 gg(GATES / 128, KSPLIT);         // (32, 4) = 128 CTAs
        lstm_wmma_ks_kernel<<<gg, 256>>>();
        lstm_reduce_point_kernel<<<BATCH * HIDDEN / 256, 256>>>(t);
    }

    {
        dim3 grid(M_ALL / 128, NCLS / 128);   // (32, 250)
        gemm_wmma_proj<<<grid, 256>>>(W_h2o, b_o, out);
    }
}